// round 5
// baseline (speedup 1.0000x reference)
#include <cuda_runtime.h>
#include <cuda_bf16.h>
#include <cstdint>
#include <math.h>

#define T_TOK 8192
#define D_DIM 4096
#define E_EXP 64
#define K_SEL 8

#define BM 64              // tokens per CTA
#define BN 128             // outputs (64 gate | 64 cls)
#define KC 64              // k per chunk
#define NCH (D_DIM / KC)   // 64 chunks
#define NTH 256

#define ROWB 144           // padded row stride in bytes (72 bf16) -> conflict-free
#define ASZ (BM * ROWB)    // 9216 B per A split tile
#define BSZ (BN * ROWB)    // 18432 B per B split tile
#define B_OFF (3 * ASZ)    // B tiles after the 3 A tiles
#define STAGE (3 * ASZ + 3 * BSZ)     // 82944 B
#define SMEM_TOTAL (2 * STAGE)        // 165888 B
#define CPAD 132           // epilogue fp32 C stride (floats)

#define NTERM 6            // bf16 split product terms (a1b1,a1b2,a2b1,a2b2,a1b3,a3b1)
#define THETA 4e-4f        // ambiguity threshold on adjacent top-9 biased-score gaps

// pre-split weights: [3 splits][128 rows][4096 k] bf16
__device__ __nv_bfloat16 g_wsplit[3u * BN * D_DIM];
// per-token "ambiguous ranking" flag
__device__ unsigned char g_flag[T_TOK];

// ----------------- helpers -----------------
static __device__ __forceinline__ uint32_t smem_u32(const void* p) {
    uint32_t a;
    asm("{ .reg .u64 t; cvta.to.shared.u64 t, %1; cvt.u32.u64 %0, t; }" : "=r"(a) : "l"(p));
    return a;
}
static __device__ __forceinline__ uint32_t b2u(__nv_bfloat162 v) {
    return *reinterpret_cast<uint32_t*>(&v);
}
static __device__ __forceinline__ void ldsm4(uint32_t (&r)[4], uint32_t addr) {
    asm volatile("ldmatrix.sync.aligned.m8n8.x4.shared.b16 {%0,%1,%2,%3}, [%4];"
                 : "=r"(r[0]), "=r"(r[1]), "=r"(r[2]), "=r"(r[3]) : "r"(addr));
}
static __device__ __forceinline__ void mma16816(float (&d)[4], const uint32_t (&a)[4],
                                                uint32_t b0, uint32_t b1) {
    asm volatile("mma.sync.aligned.m16n8k16.row.col.f32.bf16.bf16.f32 "
                 "{%0,%1,%2,%3}, {%4,%5,%6,%7}, {%8,%9}, {%0,%1,%2,%3};"
                 : "+f"(d[0]), "+f"(d[1]), "+f"(d[2]), "+f"(d[3])
                 : "r"(a[0]), "r"(a[1]), "r"(a[2]), "r"(a[3]), "r"(b0), "r"(b1));
}
static __device__ __forceinline__ void cpasync16(uint32_t dst, const void* src) {
    asm volatile("cp.async.cg.shared.global [%0], [%1], 16;" :: "r"(dst), "l"(src) : "memory");
}

// split a float4 (2 bf16x2 pairs) into hi/mid/lo bf16x2 words (exact 3-way split)
static __device__ __forceinline__ void split_f4(float4 v,
        uint32_t& h0, uint32_t& h1, uint32_t& m0, uint32_t& m1,
        uint32_t& l0, uint32_t& l1) {
    __nv_bfloat162 H0 = __floats2bfloat162_rn(v.x, v.y);
    __nv_bfloat162 H1 = __floats2bfloat162_rn(v.z, v.w);
    float r0x = v.x - __low2float(H0), r0y = v.y - __high2float(H0);
    float r1x = v.z - __low2float(H1), r1y = v.w - __high2float(H1);
    __nv_bfloat162 M0 = __floats2bfloat162_rn(r0x, r0y);
    __nv_bfloat162 M1 = __floats2bfloat162_rn(r1x, r1y);
    float s0x = r0x - __low2float(M0), s0y = r0y - __high2float(M0);
    float s1x = r1x - __low2float(M1), s1y = r1y - __high2float(M1);
    __nv_bfloat162 L0 = __floats2bfloat162_rn(s0x, s0y);
    __nv_bfloat162 L1 = __floats2bfloat162_rn(s1x, s1y);
    h0 = b2u(H0); h1 = b2u(H1); m0 = b2u(M0); m1 = b2u(M1); l0 = b2u(L0); l1 = b2u(L1);
}

// ----------------- prep: split weights once per call -----------------
__global__ __launch_bounds__(NTH)
void prep_w(const float* __restrict__ Wg, const float* __restrict__ Wc) {
    int q = blockIdx.x * NTH + threadIdx.x;       // 0..131071 (quads)
    int n = q >> 10;                              // 0..127
    int k = (q & 1023) << 2;
    const float* src = (n < E_EXP) ? (Wg + (size_t)n * D_DIM)
                                   : (Wc + (size_t)(n - E_EXP) * D_DIM);
    float4 v = *(const float4*)(src + k);
    uint32_t h0, h1, m0, m1, l0, l1;
    split_f4(v, h0, h1, m0, m1, l0, l1);
    size_t base = (size_t)n * D_DIM + k;
    *(uint2*)&g_wsplit[base]                          = make_uint2(h0, h1);
    *(uint2*)&g_wsplit[(size_t)BN * D_DIM + base]     = make_uint2(m0, m1);
    *(uint2*)&g_wsplit[2u * (size_t)BN * D_DIM + base] = make_uint2(l0, l1);
}

// ----------------- main: fused bf16x6 GEMM + router epilogue + ambiguity flag -----------------
__global__ __launch_bounds__(NTH, 1)
void router_main(const float* __restrict__ x, const float* __restrict__ es,
                 const float* __restrict__ eb, float* __restrict__ out)
{
    extern __shared__ __align__(16) char smem[];
    const uint32_t sb = smem_u32(smem);
    const int tid = threadIdx.x, lane = tid & 31, wrp = tid >> 5;
    const int t0 = blockIdx.x * BM;

    // warp tile: 32(M) x 32(N); warps 2x4
    const int m0 = (wrp >> 2) * 32;
    const int n0 = (wrp & 3) * 32;

    const int rA = (lane & 7) + ((lane >> 3) & 1) * 8;
    const int cA = (lane >> 4) & 1;
    const uint32_t aLane = sb + (uint32_t)((m0 + rA) * ROWB + cA * 16);
    const int rB = (lane & 7) + ((lane >> 4) & 1) * 8;
    const int cB = (lane >> 3) & 1;
    const uint32_t bLane = sb + B_OFF + (uint32_t)((n0 + rB) * ROWB + cB * 16);

    const int arow = tid >> 2;
    const int akb = (tid & 3) * 16;
    const float* aSrc = x + (size_t)(t0 + arow) * D_DIM + akb;

    float acc[2][4][4];
    #pragma unroll
    for (int i = 0; i < 2; ++i)
        #pragma unroll
        for (int j = 0; j < 4; ++j)
            #pragma unroll
            for (int q = 0; q < 4; ++q) acc[i][j][q] = 0.f;

    float4 av[4];

    // prologue: B(0) via cp.async into buf0; A(0) into regs
    {
        const uint32_t dbuf = sb + B_OFF;
        #pragma unroll
        for (int i = 0; i < 12; ++i) {
            int gi = tid + i * NTH;
            int sp = gi >> 10, row = (gi >> 3) & 127, seg = gi & 7;
            cpasync16(dbuf + sp * BSZ + row * ROWB + seg * 16,
                      (const char*)g_wsplit + (((size_t)sp * BN + row) * D_DIM + seg * 8) * 2);
        }
        asm volatile("cp.async.commit_group;" ::: "memory");
        #pragma unroll
        for (int i = 0; i < 4; ++i) av[i] = *(const float4*)(aSrc + i * 4);
    }

    static const int PA[NTERM] = {0, 0, 1, 1, 0, 2};
    static const int PB[NTERM] = {0, 1, 0, 1, 2, 0};

    for (int c = 0; c < NCH; ++c) {
        const int buf = c & 1;
        asm volatile("cp.async.wait_group 0;" ::: "memory");

        // convert + STS A(c)
        {
            char* abase = smem + buf * STAGE + arow * ROWB + akb * 2;
            #pragma unroll
            for (int h = 0; h < 2; ++h) {
                uint32_t H[4], M[4], L[4];
                split_f4(av[2 * h + 0], H[0], H[1], M[0], M[1], L[0], L[1]);
                split_f4(av[2 * h + 1], H[2], H[3], M[2], M[3], L[2], L[3]);
                *(uint4*)(abase + 0 * ASZ + h * 16) = make_uint4(H[0], H[1], H[2], H[3]);
                *(uint4*)(abase + 1 * ASZ + h * 16) = make_uint4(M[0], M[1], M[2], M[3]);
                *(uint4*)(abase + 2 * ASZ + h * 16) = make_uint4(L[0], L[1], L[2], L[3]);
            }
        }
        __syncthreads();

        // prefetch chunk c+1
        if (c + 1 < NCH) {
            const int kb = (c + 1) * KC;
            const uint32_t dbuf = sb + (buf ^ 1) * STAGE + B_OFF;
            #pragma unroll
            for (int i = 0; i < 12; ++i) {
                int gi = tid + i * NTH;
                int sp = gi >> 10, row = (gi >> 3) & 127, seg = gi & 7;
                cpasync16(dbuf + sp * BSZ + row * ROWB + seg * 16,
                          (const char*)g_wsplit + (((size_t)sp * BN + row) * D_DIM + kb + seg * 8) * 2);
            }
            asm volatile("cp.async.commit_group;" ::: "memory");
            #pragma unroll
            for (int i = 0; i < 4; ++i) av[i] = *(const float4*)(aSrc + kb + i * 4);
        }

        // compute chunk c
        const uint32_t aB = aLane + buf * STAGE;
        const uint32_t bB = bLane + buf * STAGE;
        #pragma unroll
        for (int ks = 0; ks < 4; ++ks) {
            uint32_t af[3][2][4], bf[3][2][4];
            #pragma unroll
            for (int s = 0; s < 3; ++s) {
                ldsm4(af[s][0], aB + s * ASZ + ks * 32);
                ldsm4(af[s][1], aB + s * ASZ + 16 * ROWB + ks * 32);
                ldsm4(bf[s][0], bB + s * BSZ + ks * 32);
                ldsm4(bf[s][1], bB + s * BSZ + 16 * ROWB + ks * 32);
            }
            #pragma unroll
            for (int p = 0; p < NTERM; ++p) {
                const int sa = PA[p], sbx = PB[p];
                #pragma unroll
                for (int mf = 0; mf < 2; ++mf)
                    #pragma unroll
                    for (int nf = 0; nf < 4; ++nf)
                        mma16816(acc[mf][nf], af[sa][mf],
                                 bf[sbx][nf >> 1][(nf & 1) * 2],
                                 bf[sbx][nf >> 1][(nf & 1) * 2 + 1]);
            }
        }
    }
    __syncthreads();

    // stage logits C[64][128] fp32 into smem
    float* Cs = (float*)smem;
    #pragma unroll
    for (int mf = 0; mf < 2; ++mf)
        #pragma unroll
        for (int nf = 0; nf < 4; ++nf) {
            int row = m0 + mf * 16 + (lane >> 2);
            int col = n0 + nf * 8 + (lane & 3) * 2;
            *(float2*)&Cs[row * CPAD + col]       = make_float2(acc[mf][nf][0], acc[mf][nf][1]);
            *(float2*)&Cs[(row + 8) * CPAD + col] = make_float2(acc[mf][nf][2], acc[mf][nf][3]);
        }
    __syncthreads();

    // epilogue: silu/abs/softmax/top-8 + ambiguity gap check (top-9)
    const float sc0 = es[lane], sc1 = es[lane + 32];
    const float bi0 = eb[lane], bi1 = eb[lane + 32];

    #pragma unroll
    for (int j = 0; j < 8; ++j) {
        const int t = wrp * 8 + j;
        const int e0 = lane, e1 = lane + 32;

        float g0 = Cs[t * CPAD + e0];
        float g1 = Cs[t * CPAD + e1];
        float c0 = Cs[t * CPAD + E_EXP + e0];
        float c1 = Cs[t * CPAD + E_EXP + e1];

        float s0 = fabsf(c0 * (g0 / (1.f + expf(-g0))));
        float s1 = fabsf(c1 * (g1 / (1.f + expf(-g1))));

        float mx = fmaxf(s0, s1);
        #pragma unroll
        for (int o = 16; o; o >>= 1) mx = fmaxf(mx, __shfl_xor_sync(0xffffffffu, mx, o));
        float x0 = expf(s0 - mx), x1 = expf(s1 - mx);
        float sm = x0 + x1;
        #pragma unroll
        for (int o = 16; o; o >>= 1) sm += __shfl_xor_sync(0xffffffffu, sm, o);
        float inv = 1.f / sm;
        float p0 = x0 * inv, p1 = x1 * inv;

        float b0 = p0 + bi0, b1 = p1 + bi1;
        float w0 = fmaf(p0, sc0, 1.f), w1 = fmaf(p1, sc1, 1.f);

        float vprev = 0.f, mingap = 1e30f;
        #pragma unroll
        for (int r = 0; r < K_SEL + 1; ++r) {
            float bv; int bi_; float bw;
            if (b0 >= b1) { bv = b0; bi_ = e0; bw = w0; }   // tie -> lower index
            else          { bv = b1; bi_ = e1; bw = w1; }
            #pragma unroll
            for (int o = 16; o; o >>= 1) {
                float ov = __shfl_xor_sync(0xffffffffu, bv, o);
                int   oi = __shfl_xor_sync(0xffffffffu, bi_, o);
                float ow = __shfl_xor_sync(0xffffffffu, bw, o);
                if (ov > bv || (ov == bv && oi < bi_)) { bv = ov; bi_ = oi; bw = ow; }
            }
            if (r > 0) mingap = fminf(mingap, vprev - bv);
            vprev = bv;
            if (r < K_SEL) {
                if (lane == 0) {
                    const size_t tg = (size_t)(t0 + t);
                    out[tg * K_SEL + r] = bw;
                    out[(size_t)T_TOK * K_SEL + tg * K_SEL + r] = (float)bi_;
                }
                if (bi_ == e0) b0 = -1e30f;
                if (bi_ == e1) b1 = -1e30f;
            }
        }
        if (lane == 0) g_flag[t0 + t] = (mingap < THETA) ? 1 : 0;
    }
}

// ----------------- recompute flagged tokens with R1-exact serial fp32 -----------------
__global__ __launch_bounds__(128)
void recompute_flagged(const float* __restrict__ x,
                       const float* __restrict__ Wg, const float* __restrict__ Wc,
                       const float* __restrict__ es, const float* __restrict__ eb,
                       float* __restrict__ out)
{
    const int t = blockIdx.x;
    if (g_flag[t] == 0) return;

    __shared__ float xs[D_DIM];
    __shared__ float logits[BN];
    const int tid = threadIdx.x, lane = tid & 31;

    #pragma unroll 4
    for (int i = tid; i < D_DIM / 4; i += 128)
        *(float4*)&xs[i * 4] = *(const float4*)(x + (size_t)t * D_DIM + i * 4);
    __syncthreads();

    // one output per thread: serial k-ascending fmaf chain (bit-exact R1 arithmetic)
    {
        const float* w = (tid < E_EXP) ? (Wg + (size_t)tid * D_DIM)
                                       : (Wc + (size_t)(tid - E_EXP) * D_DIM);
        float acc = 0.f;
        #pragma unroll 8
        for (int k = 0; k < D_DIM; ++k) acc = fmaf(xs[k], w[k], acc);
        logits[tid] = acc;
    }
    __syncthreads();

    if (tid < 32) {
        const int e0 = lane, e1 = lane + 32;
        float g0 = logits[e0], g1 = logits[e1];
        float c0 = logits[E_EXP + e0], c1 = logits[E_EXP + e1];

        float s0 = fabsf(c0 * (g0 / (1.f + expf(-g0))));
        float s1 = fabsf(c1 * (g1 / (1.f + expf(-g1))));

        float mx = fmaxf(s0, s1);
        #pragma unroll
        for (int o = 16; o; o >>= 1) mx = fmaxf(mx, __shfl_xor_sync(0xffffffffu, mx, o));
        float x0 = expf(s0 - mx), x1 = expf(s1 - mx);
        float sm = x0 + x1;
        #pragma unroll
        for (int o = 16; o; o >>= 1) sm += __shfl_xor_sync(0xffffffffu, sm, o);
        float inv = 1.f / sm;
        float p0 = x0 * inv, p1 = x1 * inv;

        float b0 = p0 + eb[e0], b1 = p1 + eb[e1];
        float w0 = fmaf(p0, es[e0], 1.f), w1 = fmaf(p1, es[e1], 1.f);

        #pragma unroll
        for (int r = 0; r < K_SEL; ++r) {
            float bv; int bi_; float bw;
            if (b0 >= b1) { bv = b0; bi_ = e0; bw = w0; }
            else          { bv = b1; bi_ = e1; bw = w1; }
            #pragma unroll
            for (int o = 16; o; o >>= 1) {
                float ov = __shfl_xor_sync(0xffffffffu, bv, o);
                int   oi = __shfl_xor_sync(0xffffffffu, bi_, o);
                float ow = __shfl_xor_sync(0xffffffffu, bw, o);
                if (ov > bv || (ov == bv && oi < bi_)) { bv = ov; bi_ = oi; bw = ow; }
            }
            if (lane == 0) {
                out[(size_t)t * K_SEL + r] = bw;
                out[(size_t)T_TOK * K_SEL + (size_t)t * K_SEL + r] = (float)bi_;
            }
            if (bi_ == e0) b0 = -1e30f;
            if (bi_ == e1) b1 = -1e30f;
        }
    }
}

extern "C" void kernel_launch(void* const* d_in, const int* in_sizes, int n_in,
                              void* d_out, int out_size)
{
    const float* x  = (const float*)d_in[0];
    const float* Wg = (const float*)d_in[1];
    const float* Wc = (const float*)d_in[2];
    const float* sc = (const float*)d_in[3];
    const float* bi = (const float*)d_in[4];
    float* out = (float*)d_out;

    cudaFuncSetAttribute(router_main, cudaFuncAttributeMaxDynamicSharedMemorySize, SMEM_TOTAL);

    prep_w<<<512, NTH>>>(Wg, Wc);
    router_main<<<T_TOK / BM, NTH, SMEM_TOTAL>>>(x, sc, bi, out);
    recompute_flagged<<<T_TOK, 128>>>(x, Wg, Wc, sc, bi, out);
}

// round 6
// speedup vs baseline: 27.3830x; 27.3830x over previous
#include <cuda_runtime.h>
#include <cuda_bf16.h>
#include <cstdint>
#include <math.h>

#define T_TOK 8192
#define D_DIM 4096
#define E_EXP 64
#define K_SEL 8

#define BM 64              // tokens per CTA
#define BN 128             // outputs (64 gate | 64 cls)
#define KC 64              // k per chunk
#define NCH (D_DIM / KC)   // 64 chunks
#define NTH 256

#define ROWB 144           // padded row stride in bytes (72 bf16) -> conflict-free
#define ASZ (BM * ROWB)    // 9216 B per A split tile
#define BSZ (BN * ROWB)    // 18432 B per B split tile
#define B_OFF (3 * ASZ)    // B tiles after the 3 A tiles
#define STAGE (3 * ASZ + 3 * BSZ)     // 82944 B
#define SMEM_TOTAL (2 * STAGE)        // 165888 B
#define CPAD 132           // epilogue fp32 C stride (floats)

#define NTERM 6            // bf16 split product terms
#define THETA 3e-6f        // ambiguity threshold (≈15x order-noise, ≪ typical gaps)

// recompute kernel smem: xs[4096] + ws[128][132] + logits
#define RC_KCH 128
#define RC_WPAD 132
#define RC_SMEM (D_DIM * 4 + BN * RC_WPAD * 4 + 512)

// pre-split weights: [3 splits][128 rows][4096 k] bf16
__device__ __nv_bfloat16 g_wsplit[3u * BN * D_DIM];
// per-token "ambiguous ranking" flag
__device__ unsigned char g_flag[T_TOK];

// ----------------- helpers -----------------
static __device__ __forceinline__ uint32_t smem_u32(const void* p) {
    uint32_t a;
    asm("{ .reg .u64 t; cvta.to.shared.u64 t, %1; cvt.u32.u64 %0, t; }" : "=r"(a) : "l"(p));
    return a;
}
static __device__ __forceinline__ uint32_t b2u(__nv_bfloat162 v) {
    return *reinterpret_cast<uint32_t*>(&v);
}
static __device__ __forceinline__ void ldsm4(uint32_t (&r)[4], uint32_t addr) {
    asm volatile("ldmatrix.sync.aligned.m8n8.x4.shared.b16 {%0,%1,%2,%3}, [%4];"
                 : "=r"(r[0]), "=r"(r[1]), "=r"(r[2]), "=r"(r[3]) : "r"(addr));
}
static __device__ __forceinline__ void mma16816(float (&d)[4], const uint32_t (&a)[4],
                                                uint32_t b0, uint32_t b1) {
    asm volatile("mma.sync.aligned.m16n8k16.row.col.f32.bf16.bf16.f32 "
                 "{%0,%1,%2,%3}, {%4,%5,%6,%7}, {%8,%9}, {%0,%1,%2,%3};"
                 : "+f"(d[0]), "+f"(d[1]), "+f"(d[2]), "+f"(d[3])
                 : "r"(a[0]), "r"(a[1]), "r"(a[2]), "r"(a[3]), "r"(b0), "r"(b1));
}
static __device__ __forceinline__ void cpasync16(uint32_t dst, const void* src) {
    asm volatile("cp.async.cg.shared.global [%0], [%1], 16;" :: "r"(dst), "l"(src) : "memory");
}

// split a float4 (2 bf16x2 pairs) into hi/mid/lo bf16x2 words (exact 3-way split)
static __device__ __forceinline__ void split_f4(float4 v,
        uint32_t& h0, uint32_t& h1, uint32_t& m0, uint32_t& m1,
        uint32_t& l0, uint32_t& l1) {
    __nv_bfloat162 H0 = __floats2bfloat162_rn(v.x, v.y);
    __nv_bfloat162 H1 = __floats2bfloat162_rn(v.z, v.w);
    float r0x = v.x - __low2float(H0), r0y = v.y - __high2float(H0);
    float r1x = v.z - __low2float(H1), r1y = v.w - __high2float(H1);
    __nv_bfloat162 M0 = __floats2bfloat162_rn(r0x, r0y);
    __nv_bfloat162 M1 = __floats2bfloat162_rn(r1x, r1y);
    float s0x = r0x - __low2float(M0), s0y = r0y - __high2float(M0);
    float s1x = r1x - __low2float(M1), s1y = r1y - __high2float(M1);
    __nv_bfloat162 L0 = __floats2bfloat162_rn(s0x, s0y);
    __nv_bfloat162 L1 = __floats2bfloat162_rn(s1x, s1y);
    h0 = b2u(H0); h1 = b2u(H1); m0 = b2u(M0); m1 = b2u(M1); l0 = b2u(L0); l1 = b2u(L1);
}

// ----------------- prep: split weights once per call -----------------
__global__ __launch_bounds__(NTH)
void prep_w(const float* __restrict__ Wg, const float* __restrict__ Wc) {
    int q = blockIdx.x * NTH + threadIdx.x;       // 0..131071 (quads)
    int n = q >> 10;                              // 0..127
    int k = (q & 1023) << 2;
    const float* src = (n < E_EXP) ? (Wg + (size_t)n * D_DIM)
                                   : (Wc + (size_t)(n - E_EXP) * D_DIM);
    float4 v = *(const float4*)(src + k);
    uint32_t h0, h1, m0, m1, l0, l1;
    split_f4(v, h0, h1, m0, m1, l0, l1);
    size_t base = (size_t)n * D_DIM + k;
    *(uint2*)&g_wsplit[base]                          = make_uint2(h0, h1);
    *(uint2*)&g_wsplit[(size_t)BN * D_DIM + base]     = make_uint2(m0, m1);
    *(uint2*)&g_wsplit[2u * (size_t)BN * D_DIM + base] = make_uint2(l0, l1);
}

// ----------------- main: fused bf16x6 GEMM + router epilogue + ambiguity flag -----------------
__global__ __launch_bounds__(NTH, 1)
void router_main(const float* __restrict__ x, const float* __restrict__ es,
                 const float* __restrict__ eb, float* __restrict__ out)
{
    extern __shared__ __align__(16) char smem[];
    const uint32_t sb = smem_u32(smem);
    const int tid = threadIdx.x, lane = tid & 31, wrp = tid >> 5;
    const int t0 = blockIdx.x * BM;

    // warp tile: 32(M) x 32(N); warps 2x4
    const int m0 = (wrp >> 2) * 32;
    const int n0 = (wrp & 3) * 32;

    const int rA = (lane & 7) + ((lane >> 3) & 1) * 8;
    const int cA = (lane >> 4) & 1;
    const uint32_t aLane = sb + (uint32_t)((m0 + rA) * ROWB + cA * 16);
    const int rB = (lane & 7) + ((lane >> 4) & 1) * 8;
    const int cB = (lane >> 3) & 1;
    const uint32_t bLane = sb + B_OFF + (uint32_t)((n0 + rB) * ROWB + cB * 16);

    const int arow = tid >> 2;
    const int akb = (tid & 3) * 16;
    const float* aSrc = x + (size_t)(t0 + arow) * D_DIM + akb;

    float acc[2][4][4];
    #pragma unroll
    for (int i = 0; i < 2; ++i)
        #pragma unroll
        for (int j = 0; j < 4; ++j)
            #pragma unroll
            for (int q = 0; q < 4; ++q) acc[i][j][q] = 0.f;

    float4 av[4];

    // prologue: B(0) via cp.async into buf0; A(0) into regs
    {
        const uint32_t dbuf = sb + B_OFF;
        #pragma unroll
        for (int i = 0; i < 12; ++i) {
            int gi = tid + i * NTH;
            int sp = gi >> 10, row = (gi >> 3) & 127, seg = gi & 7;
            cpasync16(dbuf + sp * BSZ + row * ROWB + seg * 16,
                      (const char*)g_wsplit + (((size_t)sp * BN + row) * D_DIM + seg * 8) * 2);
        }
        asm volatile("cp.async.commit_group;" ::: "memory");
        #pragma unroll
        for (int i = 0; i < 4; ++i) av[i] = *(const float4*)(aSrc + i * 4);
    }

    static const int PA[NTERM] = {0, 0, 1, 1, 0, 2};
    static const int PB[NTERM] = {0, 1, 0, 1, 2, 0};

    for (int c = 0; c < NCH; ++c) {
        const int buf = c & 1;
        asm volatile("cp.async.wait_group 0;" ::: "memory");

        // convert + STS A(c)
        {
            char* abase = smem + buf * STAGE + arow * ROWB + akb * 2;
            #pragma unroll
            for (int h = 0; h < 2; ++h) {
                uint32_t H[4], M[4], L[4];
                split_f4(av[2 * h + 0], H[0], H[1], M[0], M[1], L[0], L[1]);
                split_f4(av[2 * h + 1], H[2], H[3], M[2], M[3], L[2], L[3]);
                *(uint4*)(abase + 0 * ASZ + h * 16) = make_uint4(H[0], H[1], H[2], H[3]);
                *(uint4*)(abase + 1 * ASZ + h * 16) = make_uint4(M[0], M[1], M[2], M[3]);
                *(uint4*)(abase + 2 * ASZ + h * 16) = make_uint4(L[0], L[1], L[2], L[3]);
            }
        }
        __syncthreads();

        // prefetch chunk c+1
        if (c + 1 < NCH) {
            const int kb = (c + 1) * KC;
            const uint32_t dbuf = sb + (buf ^ 1) * STAGE + B_OFF;
            #pragma unroll
            for (int i = 0; i < 12; ++i) {
                int gi = tid + i * NTH;
                int sp = gi >> 10, row = (gi >> 3) & 127, seg = gi & 7;
                cpasync16(dbuf + sp * BSZ + row * ROWB + seg * 16,
                          (const char*)g_wsplit + (((size_t)sp * BN + row) * D_DIM + kb + seg * 8) * 2);
            }
            asm volatile("cp.async.commit_group;" ::: "memory");
            #pragma unroll
            for (int i = 0; i < 4; ++i) av[i] = *(const float4*)(aSrc + kb + i * 4);
        }

        // compute chunk c
        const uint32_t aB = aLane + buf * STAGE;
        const uint32_t bB = bLane + buf * STAGE;
        #pragma unroll
        for (int ks = 0; ks < 4; ++ks) {
            uint32_t af[3][2][4], bf[3][2][4];
            #pragma unroll
            for (int s = 0; s < 3; ++s) {
                ldsm4(af[s][0], aB + s * ASZ + ks * 32);
                ldsm4(af[s][1], aB + s * ASZ + 16 * ROWB + ks * 32);
                ldsm4(bf[s][0], bB + s * BSZ + ks * 32);
                ldsm4(bf[s][1], bB + s * BSZ + 16 * ROWB + ks * 32);
            }
            #pragma unroll
            for (int p = 0; p < NTERM; ++p) {
                const int sa = PA[p], sbx = PB[p];
                #pragma unroll
                for (int mf = 0; mf < 2; ++mf)
                    #pragma unroll
                    for (int nf = 0; nf < 4; ++nf)
                        mma16816(acc[mf][nf], af[sa][mf],
                                 bf[sbx][nf >> 1][(nf & 1) * 2],
                                 bf[sbx][nf >> 1][(nf & 1) * 2 + 1]);
            }
        }
    }
    __syncthreads();

    // stage logits C[64][128] fp32 into smem
    float* Cs = (float*)smem;
    #pragma unroll
    for (int mf = 0; mf < 2; ++mf)
        #pragma unroll
        for (int nf = 0; nf < 4; ++nf) {
            int row = m0 + mf * 16 + (lane >> 2);
            int col = n0 + nf * 8 + (lane & 3) * 2;
            *(float2*)&Cs[row * CPAD + col]       = make_float2(acc[mf][nf][0], acc[mf][nf][1]);
            *(float2*)&Cs[(row + 8) * CPAD + col] = make_float2(acc[mf][nf][2], acc[mf][nf][3]);
        }
    __syncthreads();

    // epilogue: silu/abs/softmax/top-8 + ambiguity gap check (top-9)
    const float sc0 = es[lane], sc1 = es[lane + 32];
    const float bi0 = eb[lane], bi1 = eb[lane + 32];

    #pragma unroll
    for (int j = 0; j < 8; ++j) {
        const int t = wrp * 8 + j;
        const int e0 = lane, e1 = lane + 32;

        float g0 = Cs[t * CPAD + e0];
        float g1 = Cs[t * CPAD + e1];
        float c0 = Cs[t * CPAD + E_EXP + e0];
        float c1 = Cs[t * CPAD + E_EXP + e1];

        float s0 = fabsf(c0 * (g0 / (1.f + expf(-g0))));
        float s1 = fabsf(c1 * (g1 / (1.f + expf(-g1))));

        float mx = fmaxf(s0, s1);
        #pragma unroll
        for (int o = 16; o; o >>= 1) mx = fmaxf(mx, __shfl_xor_sync(0xffffffffu, mx, o));
        float x0 = expf(s0 - mx), x1 = expf(s1 - mx);
        float sm = x0 + x1;
        #pragma unroll
        for (int o = 16; o; o >>= 1) sm += __shfl_xor_sync(0xffffffffu, sm, o);
        float inv = 1.f / sm;
        float p0 = x0 * inv, p1 = x1 * inv;

        float b0 = p0 + bi0, b1 = p1 + bi1;
        float w0 = fmaf(p0, sc0, 1.f), w1 = fmaf(p1, sc1, 1.f);

        float vprev = 0.f, mingap = 1e30f;
        #pragma unroll
        for (int r = 0; r < K_SEL + 1; ++r) {
            float bv; int bi_; float bw;
            if (b0 >= b1) { bv = b0; bi_ = e0; bw = w0; }   // tie -> lower index
            else          { bv = b1; bi_ = e1; bw = w1; }
            #pragma unroll
            for (int o = 16; o; o >>= 1) {
                float ov = __shfl_xor_sync(0xffffffffu, bv, o);
                int   oi = __shfl_xor_sync(0xffffffffu, bi_, o);
                float ow = __shfl_xor_sync(0xffffffffu, bw, o);
                if (ov > bv || (ov == bv && oi < bi_)) { bv = ov; bi_ = oi; bw = ow; }
            }
            if (r > 0) mingap = fminf(mingap, vprev - bv);
            vprev = bv;
            if (r < K_SEL) {
                if (lane == 0) {
                    const size_t tg = (size_t)(t0 + t);
                    out[tg * K_SEL + r] = bw;
                    out[(size_t)T_TOK * K_SEL + tg * K_SEL + r] = (float)bi_;
                }
                if (bi_ == e0) b0 = -1e30f;
                if (bi_ == e1) b1 = -1e30f;
            }
        }
        if (lane == 0) g_flag[t0 + t] = (mingap < THETA) ? 1 : 0;
    }
}

// ----------------- recompute flagged tokens: R1-exact serial fp32, coalesced via smem -----------------
__global__ __launch_bounds__(128)
void recompute_flagged(const float* __restrict__ x,
                       const float* __restrict__ Wg, const float* __restrict__ Wc,
                       const float* __restrict__ es, const float* __restrict__ eb,
                       float* __restrict__ out)
{
    const int t = blockIdx.x;
    if (g_flag[t] == 0) return;

    extern __shared__ __align__(16) char rsm[];
    float* xs = (float*)rsm;                                  // [4096]
    float* ws = (float*)(rsm + D_DIM * 4);                    // [128][RC_WPAD]
    float* logits = (float*)(rsm + D_DIM * 4 + BN * RC_WPAD * 4);  // [128]

    const int tid = threadIdx.x, lane = tid & 31;

    // stage x row (coalesced)
    #pragma unroll 4
    for (int i = tid; i < D_DIM / 4; i += 128)
        *(float4*)&xs[i * 4] = *(const float4*)(x + (size_t)t * D_DIM + i * 4);

    float acc = 0.f;
    const float* wrow = (tid < E_EXP) ? (Wg + (size_t)tid * D_DIM)
                                      : (Wc + (size_t)(tid - E_EXP) * D_DIM);
    // NOTE: wrow only used for pointer math below via row index; loads are cooperative.
    (void)wrow;

    for (int c = 0; c < D_DIM / RC_KCH; ++c) {
        __syncthreads();
        // cooperative coalesced load: 128 rows x 128 k of weights for this chunk
        #pragma unroll
        for (int jj = 0; jj < 32; ++jj) {
            int g = jj * 512 + tid * 4;           // over 16384 floats
            int row = g >> 7, col = g & 127;
            const float* src = (row < E_EXP) ? (Wg + (size_t)row * D_DIM)
                                             : (Wc + (size_t)(row - E_EXP) * D_DIM);
            *(float4*)&ws[row * RC_WPAD + col] = *(const float4*)(src + c * RC_KCH + col);
        }
        __syncthreads();
        // serial k-ascending fmaf chain (bit-exact R1 order)
        const float* wr = &ws[tid * RC_WPAD];
        const float* xr = &xs[c * RC_KCH];
        #pragma unroll 8
        for (int k = 0; k < RC_KCH; ++k) acc = fmaf(xr[k], wr[k], acc);
    }
    logits[tid] = acc;
    __syncthreads();

    if (tid < 32) {
        const int e0 = lane, e1 = lane + 32;
        float g0 = logits[e0], g1 = logits[e1];
        float c0 = logits[E_EXP + e0], c1 = logits[E_EXP + e1];

        float s0 = fabsf(c0 * (g0 / (1.f + expf(-g0))));
        float s1 = fabsf(c1 * (g1 / (1.f + expf(-g1))));

        float mx = fmaxf(s0, s1);
        #pragma unroll
        for (int o = 16; o; o >>= 1) mx = fmaxf(mx, __shfl_xor_sync(0xffffffffu, mx, o));
        float x0 = expf(s0 - mx), x1 = expf(s1 - mx);
        float sm = x0 + x1;
        #pragma unroll
        for (int o = 16; o; o >>= 1) sm += __shfl_xor_sync(0xffffffffu, sm, o);
        float inv = 1.f / sm;
        float p0 = x0 * inv, p1 = x1 * inv;

        float b0 = p0 + eb[e0], b1 = p1 + eb[e1];
        float w0 = fmaf(p0, es[e0], 1.f), w1 = fmaf(p1, es[e1], 1.f);

        #pragma unroll
        for (int r = 0; r < K_SEL; ++r) {
            float bv; int bi_; float bw;
            if (b0 >= b1) { bv = b0; bi_ = e0; bw = w0; }
            else          { bv = b1; bi_ = e1; bw = w1; }
            #pragma unroll
            for (int o = 16; o; o >>= 1) {
                float ov = __shfl_xor_sync(0xffffffffu, bv, o);
                int   oi = __shfl_xor_sync(0xffffffffu, bi_, o);
                float ow = __shfl_xor_sync(0xffffffffu, bw, o);
                if (ov > bv || (ov == bv && oi < bi_)) { bv = ov; bi_ = oi; bw = ow; }
            }
            if (lane == 0) {
                out[(size_t)t * K_SEL + r] = bw;
                out[(size_t)T_TOK * K_SEL + (size_t)t * K_SEL + r] = (float)bi_;
            }
            if (bi_ == e0) b0 = -1e30f;
            if (bi_ == e1) b1 = -1e30f;
        }
    }
}

extern "C" void kernel_launch(void* const* d_in, const int* in_sizes, int n_in,
                              void* d_out, int out_size)
{
    const float* x  = (const float*)d_in[0];
    const float* Wg = (const float*)d_in[1];
    const float* Wc = (const float*)d_in[2];
    const float* sc = (const float*)d_in[3];
    const float* bi = (const float*)d_in[4];
    float* out = (float*)d_out;

    cudaFuncSetAttribute(router_main, cudaFuncAttributeMaxDynamicSharedMemorySize, SMEM_TOTAL);
    cudaFuncSetAttribute(recompute_flagged, cudaFuncAttributeMaxDynamicSharedMemorySize, RC_SMEM);

    prep_w<<<512, NTH>>>(Wg, Wc);
    router_main<<<T_TOK / BM, NTH, SMEM_TOTAL>>>(x, sc, bi, out);
    recompute_flagged<<<T_TOK, 128, RC_SMEM>>>(x, Wg, Wc, sc, bi, out);
}

// round 7
// speedup vs baseline: 33.8341x; 1.2356x over previous
#include <cuda_runtime.h>
#include <cuda_fp16.h>
#include <cstdint>
#include <math.h>

#define T_TOK 8192
#define D_DIM 4096
#define E_EXP 64
#define K_SEL 8

#define BM 64              // tokens per CTA
#define BN 128             // outputs (64 gate | 64 cls)
#define KC 64              // k per chunk
#define NCH (D_DIM / KC)   // 64 chunks
#define NTH 256

#define ROWB 144           // padded row stride in bytes (72 fp16) -> conflict-free
#define ASZ (BM * ROWB)    // 9216 B per A split tile
#define BSZ (BN * ROWB)    // 18432 B per B split tile
#define B_OFF (2 * ASZ)    // B tiles after the 2 A tiles
#define STAGE (2 * ASZ + 2 * BSZ)     // 55296 B
#define SMEM_TOTAL (2 * STAGE)        // 110592 B
#define CPAD 132           // epilogue fp32 C stride (floats)

#define NTERM 3            // fp16 split product terms: a1b1, a1b2, a2b1
#define WSCALE 64.0f       // exact power-of-2 pre-scale on W (descale in epilogue)
#define INV_WSCALE 0.015625f
#define THETA 3e-6f        // ambiguity threshold (>>20x combined noise)

// recompute kernel smem: xs[4096] + ws[128][132] + logits
#define RC_KCH 128
#define RC_WPAD 132
#define RC_SMEM (D_DIM * 4 + BN * RC_WPAD * 4 + 512)

// pre-split scaled weights: [2 splits][128 rows][4096 k] fp16
__device__ __half g_wsplit[2u * BN * D_DIM];
// per-token "ambiguous ranking" flag
__device__ unsigned char g_flag[T_TOK];

// ----------------- helpers -----------------
static __device__ __forceinline__ uint32_t smem_u32(const void* p) {
    uint32_t a;
    asm("{ .reg .u64 t; cvta.to.shared.u64 t, %1; cvt.u32.u64 %0, t; }" : "=r"(a) : "l"(p));
    return a;
}
static __device__ __forceinline__ uint32_t pkh(__half a, __half b) {
    __half2 t = __halves2half2(a, b);
    return *reinterpret_cast<uint32_t*>(&t);
}
static __device__ __forceinline__ void ldsm4(uint32_t (&r)[4], uint32_t addr) {
    asm volatile("ldmatrix.sync.aligned.m8n8.x4.shared.b16 {%0,%1,%2,%3}, [%4];"
                 : "=r"(r[0]), "=r"(r[1]), "=r"(r[2]), "=r"(r[3]) : "r"(addr));
}
static __device__ __forceinline__ void mma16816(float (&d)[4], const uint32_t (&a)[4],
                                                uint32_t b0, uint32_t b1) {
    asm volatile("mma.sync.aligned.m16n8k16.row.col.f32.f16.f16.f32 "
                 "{%0,%1,%2,%3}, {%4,%5,%6,%7}, {%8,%9}, {%0,%1,%2,%3};"
                 : "+f"(d[0]), "+f"(d[1]), "+f"(d[2]), "+f"(d[3])
                 : "r"(a[0]), "r"(a[1]), "r"(a[2]), "r"(a[3]), "r"(b0), "r"(b1));
}
static __device__ __forceinline__ void cpasync16(uint32_t dst, const void* src) {
    asm volatile("cp.async.cg.shared.global [%0], [%1], 16;" :: "r"(dst), "l"(src) : "memory");
}

// split 8 fp32 into hi/lo fp16 uint4 words (2-way split, 22-bit capture)
static __device__ __forceinline__ void split8h(float4 v0, float4 v1, uint4& H, uint4& L) {
    float f[8] = {v0.x, v0.y, v0.z, v0.w, v1.x, v1.y, v1.z, v1.w};
    uint32_t h[4], l[4];
    #pragma unroll
    for (int i = 0; i < 4; ++i) {
        float x0 = f[2*i], x1 = f[2*i+1];
        __half h0 = __float2half_rn(x0), h1 = __float2half_rn(x1);
        float r0 = x0 - __half2float(h0), r1 = x1 - __half2float(h1);
        h[i] = pkh(h0, h1);
        l[i] = pkh(__float2half_rn(r0), __float2half_rn(r1));
    }
    H = make_uint4(h[0], h[1], h[2], h[3]);
    L = make_uint4(l[0], l[1], l[2], l[3]);
}

// ----------------- prep: scale by 64 and split weights once per call -----------------
__global__ __launch_bounds__(NTH)
void prep_w(const float* __restrict__ Wg, const float* __restrict__ Wc) {
    int q = blockIdx.x * NTH + threadIdx.x;       // 0..65535 (8-float groups)
    int n = q >> 9;                               // 0..127
    int k = (q & 511) << 3;
    const float* src = (n < E_EXP) ? (Wg + (size_t)n * D_DIM)
                                   : (Wc + (size_t)(n - E_EXP) * D_DIM);
    float4 v0 = *(const float4*)(src + k);
    float4 v1 = *(const float4*)(src + k + 4);
    v0.x *= WSCALE; v0.y *= WSCALE; v0.z *= WSCALE; v0.w *= WSCALE;
    v1.x *= WSCALE; v1.y *= WSCALE; v1.z *= WSCALE; v1.w *= WSCALE;
    uint4 H, L;
    split8h(v0, v1, H, L);
    size_t base = (size_t)n * D_DIM + k;
    *(uint4*)&g_wsplit[base]                      = H;
    *(uint4*)&g_wsplit[(size_t)BN * D_DIM + base] = L;
}

// ----------------- main: fused fp16x3 GEMM + router epilogue + ambiguity flag -----------------
__global__ __launch_bounds__(NTH, 1)
void router_main(const float* __restrict__ x, const float* __restrict__ es,
                 const float* __restrict__ eb, float* __restrict__ out)
{
    extern __shared__ __align__(16) char smem[];
    const uint32_t sb = smem_u32(smem);
    const int tid = threadIdx.x, lane = tid & 31, wrp = tid >> 5;
    const int t0 = blockIdx.x * BM;

    // warp tile: 32(M) x 32(N); warps 2x4
    const int m0 = (wrp >> 2) * 32;
    const int n0 = (wrp & 3) * 32;

    const int rA = (lane & 7) + ((lane >> 3) & 1) * 8;
    const int cA = (lane >> 4) & 1;
    const uint32_t aLane = sb + (uint32_t)((m0 + rA) * ROWB + cA * 16);
    const int rB = (lane & 7) + ((lane >> 4) & 1) * 8;
    const int cB = (lane >> 3) & 1;
    const uint32_t bLane = sb + B_OFF + (uint32_t)((n0 + rB) * ROWB + cB * 16);

    const int arow = tid >> 2;
    const int akb = (tid & 3) * 16;
    const float* aSrc = x + (size_t)(t0 + arow) * D_DIM + akb;

    float acc[2][4][4];
    #pragma unroll
    for (int i = 0; i < 2; ++i)
        #pragma unroll
        for (int j = 0; j < 4; ++j)
            #pragma unroll
            for (int q = 0; q < 4; ++q) acc[i][j][q] = 0.f;

    float4 av[4];

    // prologue: B(0) via cp.async into buf0; A(0) into regs
    {
        const uint32_t dbuf = sb + B_OFF;
        #pragma unroll
        for (int i = 0; i < 8; ++i) {
            int gi = tid + i * NTH;                    // 0..2047
            int sp = gi >> 10, row = (gi >> 3) & 127, seg = gi & 7;
            cpasync16(dbuf + sp * BSZ + row * ROWB + seg * 16,
                      (const char*)g_wsplit + (((size_t)sp * BN + row) * D_DIM + seg * 8) * 2);
        }
        asm volatile("cp.async.commit_group;" ::: "memory");
        #pragma unroll
        for (int i = 0; i < 4; ++i) av[i] = *(const float4*)(aSrc + i * 4);
    }

    static const int PA[NTERM] = {0, 0, 1};
    static const int PB[NTERM] = {0, 1, 0};

    for (int c = 0; c < NCH; ++c) {
        const int buf = c & 1;
        asm volatile("cp.async.wait_group 0;" ::: "memory");

        // convert + STS A(c): 2-way fp16 split
        {
            char* abase = smem + buf * STAGE + arow * ROWB + akb * 2;
            #pragma unroll
            for (int h = 0; h < 2; ++h) {
                uint4 H, L;
                split8h(av[2 * h + 0], av[2 * h + 1], H, L);
                *(uint4*)(abase + 0 * ASZ + h * 16) = H;
                *(uint4*)(abase + 1 * ASZ + h * 16) = L;
            }
        }
        __syncthreads();

        // prefetch chunk c+1
        if (c + 1 < NCH) {
            const int kb = (c + 1) * KC;
            const uint32_t dbuf = sb + (buf ^ 1) * STAGE + B_OFF;
            #pragma unroll
            for (int i = 0; i < 8; ++i) {
                int gi = tid + i * NTH;
                int sp = gi >> 10, row = (gi >> 3) & 127, seg = gi & 7;
                cpasync16(dbuf + sp * BSZ + row * ROWB + seg * 16,
                          (const char*)g_wsplit + (((size_t)sp * BN + row) * D_DIM + kb + seg * 8) * 2);
            }
            asm volatile("cp.async.commit_group;" ::: "memory");
            #pragma unroll
            for (int i = 0; i < 4; ++i) av[i] = *(const float4*)(aSrc + kb + i * 4);
        }

        // compute chunk c
        const uint32_t aB = aLane + buf * STAGE;
        const uint32_t bB = bLane + buf * STAGE;
        #pragma unroll
        for (int ks = 0; ks < 4; ++ks) {
            uint32_t af[2][2][4], bf[2][2][4];
            #pragma unroll
            for (int s = 0; s < 2; ++s) {
                ldsm4(af[s][0], aB + s * ASZ + ks * 32);
                ldsm4(af[s][1], aB + s * ASZ + 16 * ROWB + ks * 32);
                ldsm4(bf[s][0], bB + s * BSZ + ks * 32);
                ldsm4(bf[s][1], bB + s * BSZ + 16 * ROWB + ks * 32);
            }
            #pragma unroll
            for (int p = 0; p < NTERM; ++p) {
                const int sa = PA[p], sbx = PB[p];
                #pragma unroll
                for (int mf = 0; mf < 2; ++mf)
                    #pragma unroll
                    for (int nf = 0; nf < 4; ++nf)
                        mma16816(acc[mf][nf], af[sa][mf],
                                 bf[sbx][nf >> 1][(nf & 1) * 2],
                                 bf[sbx][nf >> 1][(nf & 1) * 2 + 1]);
            }
        }
    }
    __syncthreads();

    // stage logits C[64][128] fp32 into smem (descale by 1/64 here)
    float* Cs = (float*)smem;
    #pragma unroll
    for (int mf = 0; mf < 2; ++mf)
        #pragma unroll
        for (int nf = 0; nf < 4; ++nf) {
            int row = m0 + mf * 16 + (lane >> 2);
            int col = n0 + nf * 8 + (lane & 3) * 2;
            *(float2*)&Cs[row * CPAD + col] =
                make_float2(acc[mf][nf][0] * INV_WSCALE, acc[mf][nf][1] * INV_WSCALE);
            *(float2*)&Cs[(row + 8) * CPAD + col] =
                make_float2(acc[mf][nf][2] * INV_WSCALE, acc[mf][nf][3] * INV_WSCALE);
        }
    __syncthreads();

    // epilogue: silu/abs/softmax/top-8 + ambiguity gap check (top-9)
    const float sc0 = es[lane], sc1 = es[lane + 32];
    const float bi0 = eb[lane], bi1 = eb[lane + 32];

    #pragma unroll
    for (int j = 0; j < 8; ++j) {
        const int t = wrp * 8 + j;
        const int e0 = lane, e1 = lane + 32;

        float g0 = Cs[t * CPAD + e0];
        float g1 = Cs[t * CPAD + e1];
        float c0 = Cs[t * CPAD + E_EXP + e0];
        float c1 = Cs[t * CPAD + E_EXP + e1];

        float s0 = fabsf(c0 * (g0 / (1.f + expf(-g0))));
        float s1 = fabsf(c1 * (g1 / (1.f + expf(-g1))));

        float mx = fmaxf(s0, s1);
        #pragma unroll
        for (int o = 16; o; o >>= 1) mx = fmaxf(mx, __shfl_xor_sync(0xffffffffu, mx, o));
        float x0 = expf(s0 - mx), x1 = expf(s1 - mx);
        float sm = x0 + x1;
        #pragma unroll
        for (int o = 16; o; o >>= 1) sm += __shfl_xor_sync(0xffffffffu, sm, o);
        float inv = 1.f / sm;
        float p0 = x0 * inv, p1 = x1 * inv;

        float b0 = p0 + bi0, b1 = p1 + bi1;
        float w0 = fmaf(p0, sc0, 1.f), w1 = fmaf(p1, sc1, 1.f);

        float vprev = 0.f, mingap = 1e30f;
        #pragma unroll
        for (int r = 0; r < K_SEL + 1; ++r) {
            float bv; int bi_; float bw;
            if (b0 >= b1) { bv = b0; bi_ = e0; bw = w0; }   // tie -> lower index
            else          { bv = b1; bi_ = e1; bw = w1; }
            #pragma unroll
            for (int o = 16; o; o >>= 1) {
                float ov = __shfl_xor_sync(0xffffffffu, bv, o);
                int   oi = __shfl_xor_sync(0xffffffffu, bi_, o);
                float ow = __shfl_xor_sync(0xffffffffu, bw, o);
                if (ov > bv || (ov == bv && oi < bi_)) { bv = ov; bi_ = oi; bw = ow; }
            }
            if (r > 0) mingap = fminf(mingap, vprev - bv);
            vprev = bv;
            if (r < K_SEL) {
                if (lane == 0) {
                    const size_t tg = (size_t)(t0 + t);
                    out[tg * K_SEL + r] = bw;
                    out[(size_t)T_TOK * K_SEL + tg * K_SEL + r] = (float)bi_;
                }
                if (bi_ == e0) b0 = -1e30f;
                if (bi_ == e1) b1 = -1e30f;
            }
        }
        if (lane == 0) g_flag[t0 + t] = (mingap < THETA) ? 1 : 0;
    }
}

// ----------------- recompute flagged tokens: R1-exact serial fp32, coalesced via smem -----------------
__global__ __launch_bounds__(128)
void recompute_flagged(const float* __restrict__ x,
                       const float* __restrict__ Wg, const float* __restrict__ Wc,
                       const float* __restrict__ es, const float* __restrict__ eb,
                       float* __restrict__ out)
{
    const int t = blockIdx.x;
    if (g_flag[t] == 0) return;

    extern __shared__ __align__(16) char rsm[];
    float* xs = (float*)rsm;                                  // [4096]
    float* ws = (float*)(rsm + D_DIM * 4);                    // [128][RC_WPAD]
    float* logits = (float*)(rsm + D_DIM * 4 + BN * RC_WPAD * 4);  // [128]

    const int tid = threadIdx.x, lane = tid & 31;

    #pragma unroll 4
    for (int i = tid; i < D_DIM / 4; i += 128)
        *(float4*)&xs[i * 4] = *(const float4*)(x + (size_t)t * D_DIM + i * 4);

    float acc = 0.f;

    for (int c = 0; c < D_DIM / RC_KCH; ++c) {
        __syncthreads();
        #pragma unroll
        for (int jj = 0; jj < 32; ++jj) {
            int g = jj * 512 + tid * 4;
            int row = g >> 7, col = g & 127;
            const float* src = (row < E_EXP) ? (Wg + (size_t)row * D_DIM)
                                             : (Wc + (size_t)(row - E_EXP) * D_DIM);
            *(float4*)&ws[row * RC_WPAD + col] = *(const float4*)(src + c * RC_KCH + col);
        }
        __syncthreads();
        const float* wr = &ws[tid * RC_WPAD];
        const float* xr = &xs[c * RC_KCH];
        #pragma unroll 8
        for (int k = 0; k < RC_KCH; ++k) acc = fmaf(xr[k], wr[k], acc);
    }
    logits[tid] = acc;
    __syncthreads();

    if (tid < 32) {
        const int e0 = lane, e1 = lane + 32;
        float g0 = logits[e0], g1 = logits[e1];
        float c0 = logits[E_EXP + e0], c1 = logits[E_EXP + e1];

        float s0 = fabsf(c0 * (g0 / (1.f + expf(-g0))));
        float s1 = fabsf(c1 * (g1 / (1.f + expf(-g1))));

        float mx = fmaxf(s0, s1);
        #pragma unroll
        for (int o = 16; o; o >>= 1) mx = fmaxf(mx, __shfl_xor_sync(0xffffffffu, mx, o));
        float x0 = expf(s0 - mx), x1 = expf(s1 - mx);
        float sm = x0 + x1;
        #pragma unroll
        for (int o = 16; o; o >>= 1) sm += __shfl_xor_sync(0xffffffffu, sm, o);
        float inv = 1.f / sm;
        float p0 = x0 * inv, p1 = x1 * inv;

        float b0 = p0 + eb[e0], b1 = p1 + eb[e1];
        float w0 = fmaf(p0, es[e0], 1.f), w1 = fmaf(p1, es[e1], 1.f);

        #pragma unroll
        for (int r = 0; r < K_SEL; ++r) {
            float bv; int bi_; float bw;
            if (b0 >= b1) { bv = b0; bi_ = e0; bw = w0; }
            else          { bv = b1; bi_ = e1; bw = w1; }
            #pragma unroll
            for (int o = 16; o; o >>= 1) {
                float ov = __shfl_xor_sync(0xffffffffu, bv, o);
                int   oi = __shfl_xor_sync(0xffffffffu, bi_, o);
                float ow = __shfl_xor_sync(0xffffffffu, bw, o);
                if (ov > bv || (ov == bv && oi < bi_)) { bv = ov; bi_ = oi; bw = ow; }
            }
            if (lane == 0) {
                out[(size_t)t * K_SEL + r] = bw;
                out[(size_t)T_TOK * K_SEL + (size_t)t * K_SEL + r] = (float)bi_;
            }
            if (bi_ == e0) b0 = -1e30f;
            if (bi_ == e1) b1 = -1e30f;
        }
    }
}

extern "C" void kernel_launch(void* const* d_in, const int* in_sizes, int n_in,
                              void* d_out, int out_size)
{
    const float* x  = (const float*)d_in[0];
    const float* Wg = (const float*)d_in[1];
    const float* Wc = (const float*)d_in[2];
    const float* sc = (const float*)d_in[3];
    const float* bi = (const float*)d_in[4];
    float* out = (float*)d_out;

    cudaFuncSetAttribute(router_main, cudaFuncAttributeMaxDynamicSharedMemorySize, SMEM_TOTAL);
    cudaFuncSetAttribute(recompute_flagged, cudaFuncAttributeMaxDynamicSharedMemorySize, RC_SMEM);

    prep_w<<<256, NTH>>>(Wg, Wc);
    router_main<<<T_TOK / BM, NTH, SMEM_TOTAL>>>(x, sc, bi, out);
    recompute_flagged<<<T_TOK, 128, RC_SMEM>>>(x, Wg, Wc, sc, bi, out);
}